// round 4
// baseline (speedup 1.0000x reference)
#include <cuda_runtime.h>
#include <math.h>

// KarplusStrongResonator: y[t] = x[t] - a1*y[t-D1] - a2*y[t-D2]
// coeffs are 2-sparse (hard one-hot forward of gumbel straight-through).
// D1 = 61 + argmax(delay_param + gumbel), D2 = 61 + ((argmax+1) % 360).
// Min dependency distance >= 61 -> chunk-parallel IIR in shared memory.

#define T_LEN 8192
#define B_ROWS 128
#define NDELAY 360   // MAX_DELAY - MIN_DELAY
#define NT 512

__global__ __launch_bounds__(NT, 1)
void ks_resonator_kernel(const float* __restrict__ x,
                         const float* __restrict__ gumbel,
                         const float* __restrict__ dparam,
                         const float* __restrict__ fgain,
                         const float* __restrict__ refl,
                         float* __restrict__ out)
{
    extern __shared__ float smem[];
    float* ys = smem;            // [T_LEN]  output history (full row)
    float* xs = smem + T_LEN;    // [T_LEN]  input row

    __shared__ float red_v[NT];
    __shared__ int   red_i[NT];
    __shared__ float s_a1, s_a2;
    __shared__ int   s_d1, s_d2;

    const int tid = threadIdx.x;
    const int row = blockIdx.x;

    // ---- prefetch x row into shared (coalesced float4) ----
    {
        const float4* x4 = reinterpret_cast<const float4*>(x + (size_t)row * T_LEN);
        float4* xs4 = reinterpret_cast<float4*>(xs);
        #pragma unroll
        for (int i = tid; i < T_LEN / 4; i += NT) xs4[i] = x4[i];
    }

    // ---- argmax(delay_param + gumbel) via shared tree reduction ----
    {
        float v = -INFINITY;
        int   idx = tid;
        if (tid < NDELAY) v = dparam[tid] + gumbel[tid];
        red_v[tid] = v;
        red_i[tid] = idx;
        __syncthreads();
        #pragma unroll
        for (int s = NT / 2; s > 0; s >>= 1) {
            if (tid < s) {
                float v2 = red_v[tid + s];
                int   i2 = red_i[tid + s];
                float v1 = red_v[tid];
                int   i1 = red_i[tid];
                // first-max tie-break (lowest index wins), matches jnp.argmax
                if (v2 > v1 || (v2 == v1 && i2 < i1)) { red_v[tid] = v2; red_i[tid] = i2; }
            }
            __syncthreads();
        }
    }

    if (tid == 0) {
        int j = red_i[0];
        // rc = tanh(reflection); k = resonant_activation(rc, tau=0) = tanh(rc)
        float k1 = tanhf(tanhf(refl[0]));
        float k2 = tanhf(tanhf(refl[1]));
        float a1 = k1 * (1.0f - k2);
        float a2 = fminf(fmaxf(k2, -0.999f), 0.999f);
        float a1b = 0.999f - fabsf(a2);
        a1 = fminf(fmaxf(a1, -a1b), a1b);
        float g = powf(1.0f / (1.0f + expf(-fgain[0])), 0.45f);
        s_a1 = a1 * g;
        s_a2 = a2 * g;
        s_d1 = 61 + j;                    // MIN_DELAY + 1 + j
        s_d2 = 61 + ((j + 1) % NDELAY);   // rolled one-hot
    }
    __syncthreads();

    const float a1 = s_a1;
    const float a2 = s_a2;
    const int d1 = s_d1;
    const int d2 = s_d2;
    const int C  = min(d1, d2);   // dependency-free chunk size (>= 61)

    // ---- chunked IIR entirely in shared memory ----
    for (int base = 0; base < T_LEN; base += C) {
        const int end = min(base + C, T_LEN);
        for (int t = base + tid; t < end; t += NT) {
            float ya = (t >= d1) ? ys[t - d1] : 0.0f;
            float yb = (t >= d2) ? ys[t - d2] : 0.0f;
            ys[t] = fmaf(-a1, ya, fmaf(-a2, yb, xs[t]));
        }
        __syncthreads();
    }

    // ---- coalesced writeback ----
    {
        float4* o4 = reinterpret_cast<float4*>(out + (size_t)row * T_LEN);
        const float4* y4 = reinterpret_cast<const float4*>(ys);
        #pragma unroll
        for (int i = tid; i < T_LEN / 4; i += NT) o4[i] = y4[i];
    }
}

extern "C" void kernel_launch(void* const* d_in, const int* in_sizes, int n_in,
                              void* d_out, int out_size)
{
    const float* excitation = (const float*)d_in[0];  // (128,1,8192)
    const float* gumbel     = (const float*)d_in[1];  // (360,)
    const float* dparam     = (const float*)d_in[2];  // (360,)
    const float* fgain      = (const float*)d_in[3];  // (1,)
    const float* refl       = (const float*)d_in[4];  // (2,)
    float* out = (float*)d_out;                       // (128,1,8192)

    const int smem_bytes = 2 * T_LEN * sizeof(float); // 64 KB dynamic
    cudaFuncSetAttribute(ks_resonator_kernel,
                         cudaFuncAttributeMaxDynamicSharedMemorySize, smem_bytes);

    ks_resonator_kernel<<<B_ROWS, NT, smem_bytes>>>(
        excitation, gumbel, dparam, fgain, refl, out);
}

// round 6
// speedup vs baseline: 1.0226x; 1.0226x over previous
#include <cuda_runtime.h>
#include <math.h>

// KarplusStrongResonator: (1 + a1 z^-d1 + a2 z^-d2) Y = X, with
// d1 = 61 + argmax(delay_param + gumbel), d2 = 61 + ((argmax+1) % 360).
// Recurrence-doubling: multiply by (1-q)(1+q^2) -> (1 - q^4) Y = X2.
// Two fully-parallel FIR passes, then a 5-tap recurrence with min lag
// 4*min(d1,d2) >= 244 -> <=34 chunk barriers instead of ~135.

#define T_LEN 8192
#define B_ROWS 128
#define NDELAY 360
#define NT 256

__global__ __launch_bounds__(NT, 1)
void ks_resonator_kernel(const float* __restrict__ x,
                         const float* __restrict__ gumbel,
                         const float* __restrict__ dparam,
                         const float* __restrict__ fgain,
                         const float* __restrict__ refl,
                         float* __restrict__ out)
{
    extern __shared__ float smem[];
    float* A = smem;            // [T_LEN]
    float* B = smem + T_LEN;    // [T_LEN]

    __shared__ float red_v[NT];
    __shared__ int   red_i[NT];
    __shared__ float s_a1, s_a2;
    __shared__ int   s_d1, s_d2;

    const int tid = threadIdx.x;
    const int row = blockIdx.x;

    // ---- prefetch x row into A (coalesced float4) ----
    {
        const float4* x4 = reinterpret_cast<const float4*>(x + (size_t)row * T_LEN);
        float4* a4 = reinterpret_cast<float4*>(A);
        #pragma unroll
        for (int i = tid; i < T_LEN / 4; i += NT) a4[i] = x4[i];
    }

    // ---- argmax(delay_param + gumbel), first-index tie-break ----
    {
        float v = -INFINITY;
        int   idx = 0;
        for (int i = tid; i < NDELAY; i += NT) {
            float w = dparam[i] + gumbel[i];
            if (w > v) { v = w; idx = i; }   // increasing i, strict > => first max
        }
        red_v[tid] = v;
        red_i[tid] = idx;
        __syncthreads();
        #pragma unroll
        for (int s = NT / 2; s > 0; s >>= 1) {
            if (tid < s) {
                float v2 = red_v[tid + s]; int i2 = red_i[tid + s];
                float v1 = red_v[tid];     int i1 = red_i[tid];
                if (v2 > v1 || (v2 == v1 && i2 < i1)) { red_v[tid] = v2; red_i[tid] = i2; }
            }
            __syncthreads();
        }
    }

    if (tid == 0) {
        int j = red_i[0];
        float k1 = tanhf(tanhf(refl[0]));   // resonant_activation(tanh(rc), tau=0)
        float k2 = tanhf(tanhf(refl[1]));
        float a1 = k1 * (1.0f - k2);
        float a2 = fminf(fmaxf(k2, -0.999f), 0.999f);
        float a1b = 0.999f - fabsf(a2);
        a1 = fminf(fmaxf(a1, -a1b), a1b);
        float g = powf(1.0f / (1.0f + expf(-fgain[0])), 0.45f);
        s_a1 = a1 * g;
        s_a2 = a2 * g;
        s_d1 = 61 + j;
        s_d2 = 61 + ((j + 1) % NDELAY);
    }
    __syncthreads();

    const float a1 = s_a1, a2 = s_a2;
    const int d1 = s_d1, d2 = s_d2;

    // q^2 coefficients / lags
    const float c20 = a1 * a1, c21 = 2.0f * a1 * a2, c22 = a2 * a2;
    const int   l20 = 2 * d1,  l21 = d1 + d2,        l22 = 2 * d2;

    // q^4 coefficients / lags (binomial expansion of (a1 z^-d1 + a2 z^-d2)^4)
    const float q0 = a1 * a1 * a1 * a1;
    const float q1 = 4.0f * a1 * a1 * a1 * a2;
    const float q2 = 6.0f * a1 * a1 * a2 * a2;
    const float q3 = 4.0f * a1 * a2 * a2 * a2;
    const float q4 = a2 * a2 * a2 * a2;
    const int   l0 = 4 * d1;
    const int   l1 = 3 * d1 + d2;
    const int   l2 = 2 * d1 + 2 * d2;
    const int   l3 = d1 + 3 * d2;
    const int   l4 = 4 * d2;
    const int   lmax = max(l0, l4);
    const int   Cq = 4 * min(d1, d2);   // dependency-free chunk size >= 244

    // ---- pass 0: B[t] = A[t] - a1*A[t-d1] - a2*A[t-d2]  (parallel) ----
    for (int t = tid; t < T_LEN; t += NT) {
        float va = (t >= d1) ? A[t - d1] : 0.0f;
        float vb = (t >= d2) ? A[t - d2] : 0.0f;
        B[t] = fmaf(-a1, va, fmaf(-a2, vb, A[t]));
    }
    __syncthreads();

    // ---- pass 1: A[t] = B[t] + q^2 * B  (parallel) ----
    for (int t = tid; t < T_LEN; t += NT) {
        float v0 = (t >= l20) ? B[t - l20] : 0.0f;
        float v1 = (t >= l21) ? B[t - l21] : 0.0f;
        float v2 = (t >= l22) ? B[t - l22] : 0.0f;
        A[t] = fmaf(c20, v0, fmaf(c21, v1, fmaf(c22, v2, B[t])));
    }
    __syncthreads();

    // ---- recurrence: y[t] = A[t] + q^4 * y ; chunks of Cq samples ----
    // y is written into B; lags >= Cq so all reads hit prior chunks.
    for (int base = 0; base < T_LEN; base += Cq) {
        const int end = min(base + Cq, T_LEN);
        if (base >= lmax) {
            for (int t = base + tid; t < end; t += NT) {
                float acc = A[t];
                acc = fmaf(q0, B[t - l0], acc);
                acc = fmaf(q1, B[t - l1], acc);
                acc = fmaf(q2, B[t - l2], acc);
                acc = fmaf(q3, B[t - l3], acc);
                acc = fmaf(q4, B[t - l4], acc);
                B[t] = acc;
            }
        } else {
            for (int t = base + tid; t < end; t += NT) {
                float acc = A[t];
                acc = fmaf(q0, (t >= l0) ? B[t - l0] : 0.0f, acc);
                acc = fmaf(q1, (t >= l1) ? B[t - l1] : 0.0f, acc);
                acc = fmaf(q2, (t >= l2) ? B[t - l2] : 0.0f, acc);
                acc = fmaf(q3, (t >= l3) ? B[t - l3] : 0.0f, acc);
                acc = fmaf(q4, (t >= l4) ? B[t - l4] : 0.0f, acc);
                B[t] = acc;
            }
        }
        __syncthreads();
    }

    // ---- coalesced writeback ----
    {
        float4* o4 = reinterpret_cast<float4*>(out + (size_t)row * T_LEN);
        const float4* y4 = reinterpret_cast<const float4*>(B);
        #pragma unroll
        for (int i = tid; i < T_LEN / 4; i += NT) o4[i] = y4[i];
    }
}

extern "C" void kernel_launch(void* const* d_in, const int* in_sizes, int n_in,
                              void* d_out, int out_size)
{
    const float* excitation = (const float*)d_in[0];  // (128,1,8192)
    const float* gumbel     = (const float*)d_in[1];  // (360,)
    const float* dparam     = (const float*)d_in[2];  // (360,)
    const float* fgain      = (const float*)d_in[3];  // (1,)
    const float* refl       = (const float*)d_in[4];  // (2,)
    float* out = (float*)d_out;                       // (128,1,8192)

    const int smem_bytes = 2 * T_LEN * sizeof(float); // 64 KB dynamic
    cudaFuncSetAttribute(ks_resonator_kernel,
                         cudaFuncAttributeMaxDynamicSharedMemorySize, smem_bytes);

    ks_resonator_kernel<<<B_ROWS, NT, smem_bytes>>>(
        excitation, gumbel, dparam, fgain, refl, out);
}